// round 16
// baseline (speedup 1.0000x reference)
#include <cuda_runtime.h>
#include <cuda_fp16.h>

#define N_NODES 50000
#define N_EDGES 800000
#define VOCAB   4096
#define EMB_DIM 128
#define H2      256      // 2*HIDDEN
#define HIDDEN  128
#define N_POS   1024
#define NPART   32
#define AGG_GRID 2048
#define INVP    (1.f / N_POS)
#define BMW     ((N_NODES + 31) / 32)

// ---- single contiguous zero-init scratch region (one memset clears all) ----
#define CLR_DEG      0                        // int[N_NODES]
#define CLR_SELCNT   (CLR_DEG + N_NODES)      // int[N_NODES]
#define CLR_CUR      (CLR_SELCNT + N_NODES)   // int[N_NODES] (CSR fill cursor, preset to base)
#define CLR_COEF     (CLR_CUR + N_NODES)      // float[N_NODES]
#define CLR_ABARP    (CLR_COEF + N_NODES)     // float[NPART*H2]
#define CLR_SELBM    (CLR_ABARP + NPART * H2) // uint[BMW]
#define CLR_NEEDBM   (CLR_SELBM + BMW)        // uint[BMW]
#define CLR_NLIST    (CLR_NEEDBM + BMW)
#define CLR_ETOTAL   (CLR_NLIST + 1)
#define CLR_NSEL     (CLR_ETOTAL + 1)
#define CLR_TOTAL    (CLR_NSEL + 1)

__device__ __align__(16) int g_clr[CLR_TOTAL];

#define D_DEG      (g_clr + CLR_DEG)
#define D_SELCNT   (g_clr + CLR_SELCNT)
#define D_CUR      (g_clr + CLR_CUR)
#define D_COEF     ((float*)(g_clr + CLR_COEF))
#define D_ABARP    ((float*)(g_clr + CLR_ABARP))
#define D_SELBM    ((unsigned*)(g_clr + CLR_SELBM))
#define D_NEEDBM   ((unsigned*)(g_clr + CLR_NEEDBM))
#define D_NLIST    (g_clr + CLR_NLIST)
#define D_ETOTAL   (g_clr + CLR_ETOTAL)
#define D_NSEL     (g_clr + CLR_NSEL)

// ---- non-cleared scratch ----
__device__ __align__(16) __half g_embW1h[VOCAB * H2];  // emb @ W1, fp16 (2 MB)
__device__ int      g_list[N_NODES];         // compacted needed nodes
__device__ int      g_nbase[N_NODES];        // CSR base per compact idx
__device__ unsigned g_px[N_NODES];           // ((deg+1)<<12) | x  per node
__device__ int      g_sele[N_EDGES];         // edge ids with selected target
__device__ int      g_src[N_EDGES];          // raw source node id per needed edge

// ---------------- kernels ----------------------------------------------------

// Mark selected positions: multiplicity + selected bitmap + needed bitmap.
__global__ void k_mark(const int* __restrict__ pos) {
    int i = blockIdx.x * blockDim.x + threadIdx.x;
    if (i < N_POS) {
        int v = pos[i];
        atomicAdd(&D_SELCNT[v], 1);
        atomicOr(&D_SELBM[v >> 5], 1u << (v & 31));
        atomicOr(&D_NEEDBM[v >> 5], 1u << (v & 31));
    }
}

// Fused: blocks [0,256) compute embW1 = emb @ W1 (fp16 out);
// blocks [256, ...) do the edge pass: deg count + gather selected-target edges
// (bitmap test, L1-resident) + flag their sources in the needed bitmap.
#define EMB_BLKS 256
#define EDGE_BLKS ((N_EDGES / 4 + 255) / 256)
__global__ void k_big(const float* __restrict__ emb, const float* __restrict__ W1,
                      const int* __restrict__ ei) {
    __shared__ float se[16 * EMB_DIM];        // 8 KB
    int b = blockIdx.x;
    int t = threadIdx.x;
    if (b < EMB_BLKS) {
        for (int i = t; i < 16 * EMB_DIM; i += 256)
            se[i] = emb[b * 16 * EMB_DIM + i];
        __syncthreads();
        float acc[16];
#pragma unroll
        for (int r = 0; r < 16; ++r) acc[r] = 0.f;
        for (int k = 0; k < EMB_DIM; k += 4) {
            float w0 = W1[(k + 0) * H2 + t];
            float w1 = W1[(k + 1) * H2 + t];
            float w2 = W1[(k + 2) * H2 + t];
            float w3 = W1[(k + 3) * H2 + t];
#pragma unroll
            for (int r = 0; r < 16; ++r) {
                float4 s = *reinterpret_cast<const float4*>(&se[r * EMB_DIM + k]);
                acc[r] += s.x * w0 + s.y * w1 + s.z * w2 + s.w * w3;
            }
        }
#pragma unroll
        for (int r = 0; r < 16; ++r)
            g_embW1h[(b * 16 + r) * H2 + t] = __float2half(acc[r]);
    } else {
        int e4 = ((b - EMB_BLKS) * 256 + t) * 4;
        if (e4 >= N_EDGES) return;
        int4 c4 = *reinterpret_cast<const int4*>(&ei[N_EDGES + e4]);
        int cs[4] = {c4.x, c4.y, c4.z, c4.w};
#pragma unroll
        for (int k = 0; k < 4; ++k) {
            int c = cs[k];
            atomicAdd(&D_DEG[c], 1);
            if (D_SELBM[c >> 5] & (1u << (c & 31))) {      // L1-resident bitmap
                int r = ei[e4 + k];
                atomicOr(&D_NEEDBM[r >> 5], 1u << (r & 31));
                int i = atomicAdd(D_NSEL, 1);
                g_sele[i] = e4 + k;
            }
        }
    }
}

// Fused: per-node pack px + compact needed nodes (cursor preset to CSR base)
// + coef terms from the gathered selected-target edge list.
__global__ void k_coefcompact(const int* __restrict__ ei, const int* __restrict__ pos,
                              const int* __restrict__ x) {
    int tid = blockIdx.x * blockDim.x + threadIdx.x;
    int stride = gridDim.x * blockDim.x;
    int ns = *D_NSEL;
    int total = N_NODES + ns + N_POS;
    for (int i = tid; i < total; i += stride) {
        if (i < N_NODES) {
            int d = D_DEG[i];
            g_px[i] = ((unsigned)(d + 1) << 12) | (unsigned)x[i];
            if (D_NEEDBM[i >> 5] & (1u << (i & 31))) {
                int idx = atomicAdd(D_NLIST, 1);
                g_list[idx] = i;
                int base = atomicAdd(D_ETOTAL, d);
                g_nbase[idx] = base;
                D_CUR[i] = base;               // cursor starts at CSR base
            }
        } else if (i < N_NODES + ns) {
            int e = g_sele[i - N_NODES];
            int r = ei[e], c = ei[N_EDGES + e];
            float w = rsqrtf((float)(D_DEG[r] + 1)) * rsqrtf((float)(D_DEG[c] + 1));
            atomicAdd(&D_COEF[r], w * (float)D_SELCNT[c] * INVP);
        } else {
            int v = pos[i - N_NODES - ns];
            float dv = rsqrtf((float)(D_DEG[v] + 1));
            atomicAdd(&D_COEF[v], dv * dv * INVP);
        }
    }
}

// Scatter edges whose target is needed. Per accepted edge: cursor atomic +
// 4-byte write of the RAW source id (no random load here; px lookup moves to
// the aggregation kernel, which tolerates latency). 8 edges/thread.
__global__ void k_scatter2(const int* __restrict__ ei) {
    int e8 = (blockIdx.x * blockDim.x + threadIdx.x) * 8;
    if (e8 >= N_EDGES) return;
    int4 ca = *reinterpret_cast<const int4*>(&ei[N_EDGES + e8]);
    int4 cb = *reinterpret_cast<const int4*>(&ei[N_EDGES + e8 + 4]);
    int cs[8] = {ca.x, ca.y, ca.z, ca.w, cb.x, cb.y, cb.z, cb.w};
    unsigned hit = 0;
#pragma unroll
    for (int k = 0; k < 8; ++k)
        if (D_NEEDBM[cs[k] >> 5] & (1u << (cs[k] & 31))) hit |= 1u << k;
    if (!hit) return;
    int4 ra = *reinterpret_cast<const int4*>(&ei[e8]);
    int4 rb = *reinterpret_cast<const int4*>(&ei[e8 + 4]);
    int rs[8] = {ra.x, ra.y, ra.z, ra.w, rb.x, rb.y, rb.z, rb.w};
#pragma unroll
    for (int k = 0; k < 8; ++k) {
        if (hit & (1u << k)) {
            int p = atomicAdd(&D_CUR[cs[k]], 1);
            g_src[p] = rs[k];
        }
    }
}

// Per needed node v: acc = sum_e dinv_r * e_r + dv * e_self,
// h1 = relu(acc*dv + b1); tot += c_v * h1. 32 threads, lane owns 8 dims.
__global__ void k_h1abar(const float* __restrict__ b1) {
    int lane = threadIdx.x;
    float4 bb0 = reinterpret_cast<const float4*>(b1)[lane * 2];
    float4 bb1 = reinterpret_cast<const float4*>(b1)[lane * 2 + 1];
    float tot[8];
#pragma unroll
    for (int d = 0; d < 8; ++d) tot[d] = 0.f;
    const uint4* tab = reinterpret_cast<const uint4*>(g_embW1h);
    int n = *D_NLIST;
    for (int li = blockIdx.x; li < n; li += gridDim.x) {
        int v = g_list[li];
        unsigned pv = g_px[v];
        float dv = rsqrtf((float)(pv >> 12));
        int deg = (int)(pv >> 12) - 1;
        int beg = g_nbase[li];
        int end = beg + deg;
        float acc[8];
#pragma unroll
        for (int d = 0; d < 8; ++d) acc[d] = 0.f;
        for (int base = beg; base < end; base += 32) {
            int m = min(32, end - base);
            int xr = 0; float wv = 0.f;
            if (lane < m) {
                unsigned pk = g_px[g_src[base + lane]];  // seq read + L2-hit random
                xr = (int)(pk & 0xFFFu);
                wv = rsqrtf((float)(pk >> 12));
            }
            int i = 0;
            for (; i + 8 <= m; i += 8) {          // MLP = 8
                int rr[8]; float ww[8]; uint4 q[8];
#pragma unroll
                for (int u = 0; u < 8; ++u) {
                    rr[u] = __shfl_sync(0xffffffffu, xr, i + u);
                    ww[u] = __shfl_sync(0xffffffffu, wv, i + u);
                }
#pragma unroll
                for (int u = 0; u < 8; ++u) q[u] = tab[rr[u] * 32 + lane];
#pragma unroll
                for (int u = 0; u < 8; ++u) {
                    const __half2* h = reinterpret_cast<const __half2*>(&q[u]);
                    float w = ww[u];
                    float2 f0 = __half22float2(h[0]);
                    float2 f1 = __half22float2(h[1]);
                    float2 f2 = __half22float2(h[2]);
                    float2 f3 = __half22float2(h[3]);
                    acc[0] += f0.x * w; acc[1] += f0.y * w;
                    acc[2] += f1.x * w; acc[3] += f1.y * w;
                    acc[4] += f2.x * w; acc[5] += f2.y * w;
                    acc[6] += f3.x * w; acc[7] += f3.y * w;
                }
            }
            for (; i < m; ++i) {
                int   r = __shfl_sync(0xffffffffu, xr, i);
                float w = __shfl_sync(0xffffffffu, wv, i);
                uint4 q = tab[r * 32 + lane];
                const __half2* h = reinterpret_cast<const __half2*>(&q);
                float2 f0 = __half22float2(h[0]);
                float2 f1 = __half22float2(h[1]);
                float2 f2 = __half22float2(h[2]);
                float2 f3 = __half22float2(h[3]);
                acc[0] += f0.x * w; acc[1] += f0.y * w;
                acc[2] += f1.x * w; acc[3] += f1.y * w;
                acc[4] += f2.x * w; acc[5] += f2.y * w;
                acc[6] += f3.x * w; acc[7] += f3.y * w;
            }
        }
        // self loop: acc += dv * e_self, then h1 = acc*dv + b1
        {
            int xv = (int)(pv & 0xFFFu);
            uint4 q = tab[xv * 32 + lane];
            const __half2* h = reinterpret_cast<const __half2*>(&q);
            float2 f0 = __half22float2(h[0]);
            float2 f1 = __half22float2(h[1]);
            float2 f2 = __half22float2(h[2]);
            float2 f3 = __half22float2(h[3]);
            acc[0] += f0.x * dv; acc[1] += f0.y * dv;
            acc[2] += f1.x * dv; acc[3] += f1.y * dv;
            acc[4] += f2.x * dv; acc[5] += f2.y * dv;
            acc[6] += f3.x * dv; acc[7] += f3.y * dv;
        }
        float cv = D_COEF[v];
        tot[0] += fmaxf(acc[0] * dv + bb0.x, 0.f) * cv;
        tot[1] += fmaxf(acc[1] * dv + bb0.y, 0.f) * cv;
        tot[2] += fmaxf(acc[2] * dv + bb0.z, 0.f) * cv;
        tot[3] += fmaxf(acc[3] * dv + bb0.w, 0.f) * cv;
        tot[4] += fmaxf(acc[4] * dv + bb1.x, 0.f) * cv;
        tot[5] += fmaxf(acc[5] * dv + bb1.y, 0.f) * cv;
        tot[6] += fmaxf(acc[6] * dv + bb1.z, 0.f) * cv;
        tot[7] += fmaxf(acc[7] * dv + bb1.w, 0.f) * cv;
    }
    float* dst = &D_ABARP[(blockIdx.x & (NPART - 1)) * H2 + lane * 8];
#pragma unroll
    for (int d = 0; d < 8; ++d) atomicAdd(dst + d, tot[d]);
}

// Fused tail: reduce abar partials, zbar = abar@W2+b2 (recomputed per block),
// out slice = zbar@Wc + bc. 16 blocks x 256 threads.
__global__ void k_final(const float* __restrict__ W2, const float* __restrict__ b2,
                        const float* __restrict__ Wc, const float* __restrict__ bc,
                        float* __restrict__ out) {
    __shared__ float sabar[H2];
    __shared__ float sz[HIDDEN];
    int t = threadIdx.x;
    float s = 0.f;
#pragma unroll 8
    for (int p = 0; p < NPART; ++p)
        s += D_ABARP[p * H2 + t];
    sabar[t] = s;
    __syncthreads();
    if (t < HIDDEN) {
        float acc = b2[t];
#pragma unroll 8
        for (int k = 0; k < H2; ++k)
            acc += sabar[k] * W2[k * HIDDEN + t];
        sz[t] = acc;
    }
    __syncthreads();
    int c = blockIdx.x * 256 + t;
    float acc = bc[c];
#pragma unroll 8
    for (int j = 0; j < HIDDEN; ++j)
        acc += sz[j] * Wc[j * VOCAB + c];
    out[c] = acc;
}

// ---------------- launch ------------------------------------------------------

extern "C" void kernel_launch(void* const* d_in, const int* in_sizes, int n_in,
                              void* d_out, int out_size) {
    const int*   x    = (const int*)  d_in[0];   // (N_NODES,1) int32
    const int*   ei   = (const int*)  d_in[1];   // (2,N_EDGES) int32
    const int*   pos  = (const int*)  d_in[2];   // (N_POS,)    int32
    const float* emb  = (const float*)d_in[3];   // (4096,128)
    const float* W1   = (const float*)d_in[4];   // (128,256)
    const float* b1   = (const float*)d_in[5];   // (256,)
    const float* W2   = (const float*)d_in[6];   // (256,128)
    const float* b2   = (const float*)d_in[7];   // (128,)
    const float* Wc   = (const float*)d_in[8];   // (128,4096)
    const float* bc   = (const float*)d_in[9];   // (4096,)
    float* out = (float*)d_out;                  // (1,4096)

    void* clrp = nullptr;
    cudaGetSymbolAddress(&clrp, g_clr);
    cudaMemsetAsync(clrp, 0, CLR_TOTAL * sizeof(int));

    k_mark<<<(N_POS + 255) / 256, 256>>>(pos);
    k_big<<<EMB_BLKS + EDGE_BLKS, 256>>>(emb, W1, ei);
    k_coefcompact<<<512, 256>>>(ei, pos, x);
    k_scatter2<<<(N_EDGES / 8 + 255) / 256, 256>>>(ei);
    k_h1abar<<<AGG_GRID, 32>>>(b1);
    k_final<<<VOCAB / 256, 256>>>(W2, b2, Wc, bc, out);
}